// round 6
// baseline (speedup 1.0000x reference)
#include <cuda_runtime.h>

#define NR 512
#define DD 768
#define EPSF 1e-8f
#define LN2F 0.69314718055994530942f
#define LAMBDF 1.0f

#define TI 16                // pair tile is 16x16
#define BK 128
#define PADF 132             // 128 + 4 floats -> float4 stride 33 (odd)
#define PAD4 (PADF/4)        // 33
#define NBLK ((NR/TI)*(NR/TI))   // 1024 pair blocks
#define NT 64                // threads per pair block (8x8, each does 2x2 pairs)

// Raw MUFU.LG2, no denormal fixup. Inputs here are in [2e-8, 2] — never denormal,
// so ftz is exact. Avoids the non-ftz lg2.approx fixup sequence ptxas emits
// without fast-math (the suspected 2x instruction bloat).
__device__ __forceinline__ float flg2(float x) {
    float r;
    asm("lg2.approx.ftz.f32 %0, %1;" : "=f"(r) : "f"(x));
    return r;
}
__device__ __forceinline__ float fex2(float x) {
    float r;
    asm("ex2.approx.ftz.f32 %0, %1;" : "=f"(r) : "f"(x));
    return r;
}

// Scratch (no cudaMalloc allowed)
__device__ float    g_P1[NR * DD];   // p1 + eps
__device__ float    g_P2[NR * DD];   // p2 + eps
__device__ float    g_H1[NR];        // sum p1*ln(p1+eps)
__device__ float    g_H2[NR];
__device__ float    g_ptot[NBLK];    // per-block tot partials
__device__ float    g_pdia[NBLK];    // per-block dia partials
__device__ unsigned g_counter = 0;   // ticket for last-block finalize (self-resetting)

// One block per row; blocks [0,512) -> z1, [512,1024) -> z2. 256 threads, 3 elems each.
__global__ void softmax_kernel(const float* __restrict__ z1,
                               const float* __restrict__ z2) {
    const int  row   = blockIdx.x & (NR - 1);
    const bool first = blockIdx.x < NR;
    const float* src = (first ? z1 : z2) + row * DD;
    float*       dst = (first ? g_P1 : g_P2) + row * DD;
    float*      hrow = first ? g_H1 : g_H2;

    const int tid = threadIdx.x;
    const int w = tid >> 5, l = tid & 31;

    float x0 = src[tid];
    float x1 = src[tid + 256];
    float x2 = src[tid + 512];

    __shared__ float sred[8];

    // --- max reduce ---
    float mx = fmaxf(x0, fmaxf(x1, x2));
    #pragma unroll
    for (int o = 16; o; o >>= 1) mx = fmaxf(mx, __shfl_xor_sync(0xffffffffu, mx, o));
    if (l == 0) sred[w] = mx;
    __syncthreads();
    mx = sred[0];
    #pragma unroll
    for (int i = 1; i < 8; i++) mx = fmaxf(mx, sred[i]);
    __syncthreads();

    // --- exp + sum reduce (exp(x) = ex2(x * log2 e)) ---
    const float L2E = 1.4426950408889634f;
    float e0 = fex2((x0 - mx) * L2E);
    float e1 = fex2((x1 - mx) * L2E);
    float e2 = fex2((x2 - mx) * L2E);
    float s = e0 + e1 + e2;
    #pragma unroll
    for (int o = 16; o; o >>= 1) s += __shfl_xor_sync(0xffffffffu, s, o);
    if (l == 0) sred[w] = s;
    __syncthreads();
    s = sred[0];
    #pragma unroll
    for (int i = 1; i < 8; i++) s += sred[i];
    __syncthreads();

    const float inv = 1.0f / s;
    float p0 = e0 * inv, p1 = e1 * inv, p2 = e2 * inv;
    float a0 = p0 + EPSF, a1 = p1 + EPSF, a2 = p2 + EPSF;
    dst[tid]       = a0;
    dst[tid + 256] = a1;
    dst[tid + 512] = a2;

    // --- H = sum p * ln(p+eps) ---
    float h = p0 * flg2(a0) + p1 * flg2(a1) + p2 * flg2(a2);
    #pragma unroll
    for (int o = 16; o; o >>= 1) h += __shfl_xor_sync(0xffffffffu, h, o);
    if (l == 0) sred[w] = h;
    __syncthreads();
    if (tid == 0) {
        float hs = 0.f;
        #pragma unroll
        for (int i = 0; i < 8; i++) hs += sred[i];
        hrow[row] = hs * LN2F;
    }
}

// 16x16 pair tile per block, 64 threads (8x8), each thread a 2x2 pair micro-tile.
// C(i,j) = ln2 * (T1 - 2eps*T2 - 2); jsd = 0.5*(H1 + H2 - C).
// T1 split into even/odd component accumulators (384 terms each) for accuracy.
__global__ void __launch_bounds__(NT) pair_kernel(float* __restrict__ out) {
    __shared__ float As[TI * PADF];
    __shared__ float Bs[TI * PADF];
    __shared__ float rt2[2], rd2[2];
    __shared__ bool  s_last;

    const int tid = threadIdx.x;
    const int ib = blockIdx.x & 31;   // 512/16 = 32 tiles per dim
    const int jb = blockIdx.x >> 5;
    const int ti = tid & 7;           // i rows: ti, ti+8
    const int tj = tid >> 3;          // j rows: tj, tj+8

    const float4* gp1 = (const float4*)(g_P1 + ib * TI * DD);
    const float4* gp2 = (const float4*)(g_P2 + jb * TI * DD);

    // T1 even/odd per pair (e: x,z comps; o: y,w comps), T2 single per pair
    float T1e00 = 0.f, T1e01 = 0.f, T1e10 = 0.f, T1e11 = 0.f;
    float T1o00 = 0.f, T1o01 = 0.f, T1o10 = 0.f, T1o11 = 0.f;
    float T200 = 0.f, T201 = 0.f, T210 = 0.f, T211 = 0.f;

    #pragma unroll 1
    for (int kb = 0; kb < DD / BK; kb++) {
        // stage 16 x 128 chunk of each matrix: 512 float4 each, 64 threads -> 8 apiece
        #pragma unroll
        for (int r = 0; r < 8; r++) {
            int idx = tid + r * NT;            // 0..511
            int row = idx >> 5;                // /32
            int c   = idx & 31;
            ((float4*)As)[row * PAD4 + c] = gp1[row * (DD / 4) + kb * (BK / 4) + c];
        }
        #pragma unroll
        for (int r = 0; r < 8; r++) {
            int idx = tid + r * NT;
            int row = idx >> 5;
            int c   = idx & 31;
            ((float4*)Bs)[row * PAD4 + c] = gp2[row * (DD / 4) + kb * (BK / 4) + c];
        }
        __syncthreads();

        const float4* a0p = (const float4*)(As + ti * PADF);
        const float4* a1p = (const float4*)(As + (ti + 8) * PADF);
        const float4* b0p = (const float4*)(Bs + tj * PADF);
        const float4* b1p = (const float4*)(Bs + (tj + 8) * PADF);

        #pragma unroll 4
        for (int k = 0; k < BK / 4; k++) {
            float4 a0 = a0p[k], a1 = a1p[k];
            float4 b0 = b0p[k], b1 = b1p[k];

            #define PAIRSTEP(ax, bx, P)                                     \
            {                                                               \
                float s00 = a0.ax + b0.bx;  float u00 = flg2(s00);          \
                float s01 = a0.ax + b1.bx;  float u01 = flg2(s01);          \
                float s10 = a1.ax + b0.bx;  float u10 = flg2(s10);          \
                float s11 = a1.ax + b1.bx;  float u11 = flg2(s11);          \
                T1##P##00 = fmaf(s00, u00, T1##P##00); T200 += u00;         \
                T1##P##01 = fmaf(s01, u01, T1##P##01); T201 += u01;         \
                T1##P##10 = fmaf(s10, u10, T1##P##10); T210 += u10;         \
                T1##P##11 = fmaf(s11, u11, T1##P##11); T211 += u11;         \
            }
            PAIRSTEP(x, x, e)
            PAIRSTEP(y, y, o)
            PAIRSTEP(z, z, e)
            PAIRSTEP(w, w, o)
            #undef PAIRSTEP
        }
        __syncthreads();
    }

    const int gi0 = ib * TI + ti,  gi1 = gi0 + 8;
    const int gj0 = jb * TI + tj,  gj1 = gj0 + 8;

    const float h10 = g_H1[gi0], h11 = g_H1[gi1];
    const float h20 = g_H2[gj0], h21 = g_H2[gj1];

    #define JSD(T1v, T2v, hi, hj) \
        (0.5f * ((hi) + (hj) - LN2F * ((T1v) - 2.0f * EPSF * (T2v) - 2.0f)))
    float j00 = JSD(T1e00 + T1o00, T200, h10, h20);
    float j01 = JSD(T1e01 + T1o01, T201, h10, h21);
    float j10 = JSD(T1e10 + T1o10, T210, h11, h20);
    float j11 = JSD(T1e11 + T1o11, T211, h11, h21);
    #undef JSD

    float t = (j00 + j01) + (j10 + j11);
    float d = 0.f;
    if (gi0 == gj0) d += j00;
    if (gi0 == gj1) d += j01;
    if (gi1 == gj0) d += j10;
    if (gi1 == gj1) d += j11;

    const int w = tid >> 5, l = tid & 31;
    #pragma unroll
    for (int o = 16; o; o >>= 1) {
        t += __shfl_xor_sync(0xffffffffu, t, o);
        d += __shfl_xor_sync(0xffffffffu, d, o);
    }
    if (l == 0) { rt2[w] = t; rd2[w] = d; }
    __syncthreads();

    // Per-block partial + ticket (canonical threadFenceReduction pattern)
    if (tid == 0) {
        g_ptot[blockIdx.x] = rt2[0] + rt2[1];
        g_pdia[blockIdx.x] = rd2[0] + rd2[1];
        __threadfence();
        unsigned ticket = atomicAdd(&g_counter, 1u);
        s_last = (ticket == (unsigned)(gridDim.x - 1));
    }
    __syncthreads();

    if (s_last) {
        // Last block: reduce all NBLK partials in double precision.
        double dt = 0.0, dd_ = 0.0;
        for (int i = tid; i < NBLK; i += NT) {
            float pt = *(volatile float*)&g_ptot[i];
            float pd = *(volatile float*)&g_pdia[i];
            dt  += (double)pt;
            dd_ += (double)pd;
        }
        #pragma unroll
        for (int o = 16; o; o >>= 1) {
            dt  += __shfl_xor_sync(0xffffffffu, dt, o);
            dd_ += __shfl_xor_sync(0xffffffffu, dd_, o);
        }
        __shared__ double dtot[2], ddia[2];
        if (l == 0) { dtot[w] = dt; ddia[w] = dd_; }
        __syncthreads();
        if (tid == 0) {
            double tot  = dtot[0] + dtot[1];
            double dia_ = ddia[0] + ddia[1];
            double pos = dia_ / (double)NR;
            double neg = -(tot - dia_) / ((double)NR * NR - NR);
            out[0] = (float)(pos + (double)LAMBDF * neg);
            g_counter = 0;   // reset for next graph replay
        }
    }
}

extern "C" void kernel_launch(void* const* d_in, const int* in_sizes, int n_in,
                              void* d_out, int out_size) {
    const float* z1 = (const float*)d_in[0];
    const float* z2 = (const float*)d_in[1];
    float* out = (float*)d_out;

    softmax_kernel<<<2 * NR, 256>>>(z1, z2);
    pair_kernel<<<NBLK, NT>>>(out);
}

// round 8
// speedup vs baseline: 1.2397x; 1.2397x over previous
#include <cuda_runtime.h>

#define NR 512
#define DD 768
#define EPSF 1e-8f
#define LN2F 0.69314718055994530942f
#define LAMBDF 1.0f

#define TI 16                // pair tile is 16x16
#define BK 128
#define PADF 132             // 128 + 4 floats -> float4 stride 33 (odd)
#define PAD4 (PADF/4)        // 33
#define NBLK ((NR/TI)*(NR/TI))   // 1024 pair blocks
#define NT 128               // 4 warps -> all 4 SMSPs; each thread 2x1 pairs

// Raw MUFU.LG2/EX2, ftz (exact for our range s in [2e-8, 2]); avoids the
// non-ftz denormal fixup sequence (confirmed R6: alu 29%->0.8%).
__device__ __forceinline__ float flg2(float x) {
    float r;
    asm("lg2.approx.ftz.f32 %0, %1;" : "=f"(r) : "f"(x));
    return r;
}
__device__ __forceinline__ float fex2(float x) {
    float r;
    asm("ex2.approx.ftz.f32 %0, %1;" : "=f"(r) : "f"(x));
    return r;
}

// Scratch (no cudaMalloc allowed)
__device__ float    g_P1[NR * DD];   // p1 + eps
__device__ float    g_P2[NR * DD];   // p2 + eps
__device__ float    g_H1[NR];        // sum p1*ln(p1+eps)
__device__ float    g_H2[NR];
__device__ float    g_ptot[NBLK];    // per-block tot partials
__device__ float    g_pdia[NBLK];    // per-block dia partials
__device__ unsigned g_counter = 0;   // ticket for last-block finalize (self-resetting)

// One block per row; blocks [0,512) -> z1, [512,1024) -> z2. 256 threads, 3 elems each.
__global__ void softmax_kernel(const float* __restrict__ z1,
                               const float* __restrict__ z2) {
    const int  row   = blockIdx.x & (NR - 1);
    const bool first = blockIdx.x < NR;
    const float* src = (first ? z1 : z2) + row * DD;
    float*       dst = (first ? g_P1 : g_P2) + row * DD;
    float*      hrow = first ? g_H1 : g_H2;

    const int tid = threadIdx.x;
    const int w = tid >> 5, l = tid & 31;

    float x0 = src[tid];
    float x1 = src[tid + 256];
    float x2 = src[tid + 512];

    __shared__ float sred[8];

    // --- max reduce ---
    float mx = fmaxf(x0, fmaxf(x1, x2));
    #pragma unroll
    for (int o = 16; o; o >>= 1) mx = fmaxf(mx, __shfl_xor_sync(0xffffffffu, mx, o));
    if (l == 0) sred[w] = mx;
    __syncthreads();
    mx = sred[0];
    #pragma unroll
    for (int i = 1; i < 8; i++) mx = fmaxf(mx, sred[i]);
    __syncthreads();

    // --- exp + sum reduce (exp(x) = ex2(x * log2 e)) ---
    const float L2E = 1.4426950408889634f;
    float e0 = fex2((x0 - mx) * L2E);
    float e1 = fex2((x1 - mx) * L2E);
    float e2 = fex2((x2 - mx) * L2E);
    float s = e0 + e1 + e2;
    #pragma unroll
    for (int o = 16; o; o >>= 1) s += __shfl_xor_sync(0xffffffffu, s, o);
    if (l == 0) sred[w] = s;
    __syncthreads();
    s = sred[0];
    #pragma unroll
    for (int i = 1; i < 8; i++) s += sred[i];
    __syncthreads();

    const float inv = 1.0f / s;
    float p0 = e0 * inv, p1 = e1 * inv, p2 = e2 * inv;
    float a0 = p0 + EPSF, a1 = p1 + EPSF, a2 = p2 + EPSF;
    dst[tid]       = a0;
    dst[tid + 256] = a1;
    dst[tid + 512] = a2;

    // --- H = sum p * ln(p+eps) ---
    float h = p0 * flg2(a0) + p1 * flg2(a1) + p2 * flg2(a2);
    #pragma unroll
    for (int o = 16; o; o >>= 1) h += __shfl_xor_sync(0xffffffffu, h, o);
    if (l == 0) sred[w] = h;
    __syncthreads();
    if (tid == 0) {
        float hs = 0.f;
        #pragma unroll
        for (int i = 0; i < 8; i++) hs += sred[i];
        hrow[row] = hs * LN2F;
    }
}

// 16x16 pair tile per block, 128 threads (4 warps), each thread a 2x1 micro-tile
// (i rows ti, ti+8; one j). 4 warps covers all SMSPs; ~7 blocks/SM -> ~28 warps/SM
// keeps MUFU.LG2 (the sole floor) saturated.
// C(i,j) = ln2*(T1 - 2eps*T2 - 2); jsd = 0.5*(H1 + H2 - C).
// T1 and T2 both split even/odd k (384-term fp32 accumulators) for accuracy.
__global__ void __launch_bounds__(NT) pair_kernel(float* __restrict__ out) {
    __shared__ float As[TI * PADF];
    __shared__ float Bs[TI * PADF];
    __shared__ float rt4[4], rd4[4];
    __shared__ bool  s_last;

    const int tid = threadIdx.x;
    const int ib = blockIdx.x & 31;   // 512/16 = 32 tiles per dim
    const int jb = blockIdx.x >> 5;
    const int ti = tid & 7;           // i rows: ti, ti+8
    const int tj = tid >> 3;          // j row: tj (0..15)

    const float4* gp1 = (const float4*)(g_P1 + ib * TI * DD);
    const float4* gp2 = (const float4*)(g_P2 + jb * TI * DD);

    // per pair (p = i0/i1): T1 even/odd, T2 even/odd
    float T1e0 = 0.f, T1o0 = 0.f, T1e1 = 0.f, T1o1 = 0.f;
    float T2e0 = 0.f, T2o0 = 0.f, T2e1 = 0.f, T2o1 = 0.f;

    #pragma unroll 1
    for (int kb = 0; kb < DD / BK; kb++) {
        // stage 16 x 128 chunk of each matrix: 512 float4 each, 128 threads -> 4 apiece
        #pragma unroll
        for (int r = 0; r < 4; r++) {
            int idx = tid + r * NT;            // 0..511
            int row = idx >> 5;                // /32
            int c   = idx & 31;
            ((float4*)As)[row * PAD4 + c] = gp1[row * (DD / 4) + kb * (BK / 4) + c];
        }
        #pragma unroll
        for (int r = 0; r < 4; r++) {
            int idx = tid + r * NT;
            int row = idx >> 5;
            int c   = idx & 31;
            ((float4*)Bs)[row * PAD4 + c] = gp2[row * (DD / 4) + kb * (BK / 4) + c];
        }
        __syncthreads();

        const float4* a0p = (const float4*)(As + ti * PADF);
        const float4* a1p = (const float4*)(As + (ti + 8) * PADF);
        const float4* bp  = (const float4*)(Bs + tj * PADF);

        #pragma unroll 8
        for (int k = 0; k < BK / 4; k++) {
            float4 a0 = a0p[k], a1 = a1p[k];
            float4 b  = bp[k];

            #define PAIRSTEP(cx, P)                                 \
            {                                                       \
                float s0 = a0.cx + b.cx;  float u0 = flg2(s0);      \
                float s1 = a1.cx + b.cx;  float u1 = flg2(s1);      \
                T1##P##0 = fmaf(s0, u0, T1##P##0); T2##P##0 += u0;  \
                T1##P##1 = fmaf(s1, u1, T1##P##1); T2##P##1 += u1;  \
            }
            PAIRSTEP(x, e)
            PAIRSTEP(y, o)
            PAIRSTEP(z, e)
            PAIRSTEP(w, o)
            #undef PAIRSTEP
        }
        __syncthreads();
    }

    const int gi0 = ib * TI + ti,  gi1 = gi0 + 8;
    const int gj  = jb * TI + tj;

    const float h10 = g_H1[gi0], h11 = g_H1[gi1];
    const float h2j = g_H2[gj];

    #define JSD(T1v, T2v, hi, hj) \
        (0.5f * ((hi) + (hj) - LN2F * ((T1v) - 2.0f * EPSF * (T2v) - 2.0f)))
    float j0 = JSD(T1e0 + T1o0, T2e0 + T2o0, h10, h2j);
    float j1 = JSD(T1e1 + T1o1, T2e1 + T2o1, h11, h2j);
    #undef JSD

    float t = j0 + j1;
    float d = 0.f;
    if (gi0 == gj) d += j0;
    if (gi1 == gj) d += j1;

    const int w = tid >> 5, l = tid & 31;
    #pragma unroll
    for (int o = 16; o; o >>= 1) {
        t += __shfl_xor_sync(0xffffffffu, t, o);
        d += __shfl_xor_sync(0xffffffffu, d, o);
    }
    if (l == 0) { rt4[w] = t; rd4[w] = d; }
    __syncthreads();

    // Per-block partial + ticket (canonical threadFenceReduction pattern)
    if (tid == 0) {
        g_ptot[blockIdx.x] = (rt4[0] + rt4[1]) + (rt4[2] + rt4[3]);
        g_pdia[blockIdx.x] = (rd4[0] + rd4[1]) + (rd4[2] + rd4[3]);
        __threadfence();
        unsigned ticket = atomicAdd(&g_counter, 1u);
        s_last = (ticket == (unsigned)(gridDim.x - 1));
    }
    __syncthreads();

    if (s_last) {
        // Last block: reduce all NBLK partials in double precision.
        double dt = 0.0, dd_ = 0.0;
        for (int i = tid; i < NBLK; i += NT) {
            float pt = *(volatile float*)&g_ptot[i];
            float pd = *(volatile float*)&g_pdia[i];
            dt  += (double)pt;
            dd_ += (double)pd;
        }
        #pragma unroll
        for (int o = 16; o; o >>= 1) {
            dt  += __shfl_xor_sync(0xffffffffu, dt, o);
            dd_ += __shfl_xor_sync(0xffffffffu, dd_, o);
        }
        __shared__ double dtot[4], ddia[4];
        if (l == 0) { dtot[w] = dt; ddia[w] = dd_; }
        __syncthreads();
        if (tid == 0) {
            double tot  = (dtot[0] + dtot[1]) + (dtot[2] + dtot[3]);
            double dia_ = (ddia[0] + ddia[1]) + (ddia[2] + ddia[3]);
            double pos = dia_ / (double)NR;
            double neg = -(tot - dia_) / ((double)NR * NR - NR);
            out[0] = (float)(pos + (double)LAMBDF * neg);
            g_counter = 0;   // reset for next graph replay
        }
    }
}

extern "C" void kernel_launch(void* const* d_in, const int* in_sizes, int n_in,
                              void* d_out, int out_size) {
    const float* z1 = (const float*)d_in[0];
    const float* z2 = (const float*)d_in[1];
    float* out = (float*)d_out;

    softmax_kernel<<<2 * NR, 256>>>(z1, z2);
    pair_kernel<<<NBLK, NT>>>(out);
}

// round 9
// speedup vs baseline: 1.2694x; 1.0240x over previous
#include <cuda_runtime.h>

#define NR 512
#define DD 768
#define EPSF 1e-8f
#define LN2F 0.69314718055994530942f
#define LAMBDF 1.0f

#define TI 16                // pair tile is 16x16
#define BK 128
#define PADF 132             // 128 + 4 floats -> float4 stride 33 (odd)
#define PAD4 (PADF/4)        // 33
#define NBLK ((NR/TI)*(NR/TI))   // 1024 pair blocks
#define NT 128               // 4 warps -> all 4 SMSPs; each thread 2x1 pairs

// Raw MUFU.LG2/EX2, ftz (exact for our range s in [2e-8, 2]); avoids the
// non-ftz denormal fixup sequence (confirmed R6: alu 29%->0.8%).
__device__ __forceinline__ float flg2(float x) {
    float r;
    asm("lg2.approx.ftz.f32 %0, %1;" : "=f"(r) : "f"(x));
    return r;
}
__device__ __forceinline__ float fex2(float x) {
    float r;
    asm("ex2.approx.ftz.f32 %0, %1;" : "=f"(r) : "f"(x));
    return r;
}

// Scratch (no cudaMalloc allowed)
__device__ float    g_P1[NR * DD];   // p1 + eps
__device__ float    g_P2[NR * DD];   // p2 + eps
__device__ float    g_H1[NR];        // sum p1*ln(p1+eps)
__device__ float    g_H2[NR];
__device__ float    g_ptot[NBLK];    // per-block tot partials
__device__ float    g_pdia[NBLK];    // per-block dia partials
__device__ unsigned g_counter = 0;   // ticket for last-block finalize (self-resetting)

// One block per row; blocks [0,512) -> z1, [512,1024) -> z2. 256 threads, 3 elems each.
__global__ void softmax_kernel(const float* __restrict__ z1,
                               const float* __restrict__ z2) {
    const int  row   = blockIdx.x & (NR - 1);
    const bool first = blockIdx.x < NR;
    const float* src = (first ? z1 : z2) + row * DD;
    float*       dst = (first ? g_P1 : g_P2) + row * DD;
    float*      hrow = first ? g_H1 : g_H2;

    const int tid = threadIdx.x;
    const int w = tid >> 5, l = tid & 31;

    float x0 = src[tid];
    float x1 = src[tid + 256];
    float x2 = src[tid + 512];

    __shared__ float sred[8];

    // --- max reduce ---
    float mx = fmaxf(x0, fmaxf(x1, x2));
    #pragma unroll
    for (int o = 16; o; o >>= 1) mx = fmaxf(mx, __shfl_xor_sync(0xffffffffu, mx, o));
    if (l == 0) sred[w] = mx;
    __syncthreads();
    mx = sred[0];
    #pragma unroll
    for (int i = 1; i < 8; i++) mx = fmaxf(mx, sred[i]);
    __syncthreads();

    // --- exp + sum reduce (exp(x) = ex2(x * log2 e)) ---
    const float L2E = 1.4426950408889634f;
    float e0 = fex2((x0 - mx) * L2E);
    float e1 = fex2((x1 - mx) * L2E);
    float e2 = fex2((x2 - mx) * L2E);
    float s = e0 + e1 + e2;
    #pragma unroll
    for (int o = 16; o; o >>= 1) s += __shfl_xor_sync(0xffffffffu, s, o);
    if (l == 0) sred[w] = s;
    __syncthreads();
    s = sred[0];
    #pragma unroll
    for (int i = 1; i < 8; i++) s += sred[i];
    __syncthreads();

    const float inv = 1.0f / s;
    float p0 = e0 * inv, p1 = e1 * inv, p2 = e2 * inv;
    float a0 = p0 + EPSF, a1 = p1 + EPSF, a2 = p2 + EPSF;
    dst[tid]       = a0;
    dst[tid + 256] = a1;
    dst[tid + 512] = a2;

    // --- H = sum p * ln(p+eps) ---
    float h = p0 * flg2(a0) + p1 * flg2(a1) + p2 * flg2(a2);
    #pragma unroll
    for (int o = 16; o; o >>= 1) h += __shfl_xor_sync(0xffffffffu, h, o);
    if (l == 0) sred[w] = h;
    __syncthreads();
    if (tid == 0) {
        float hs = 0.f;
        #pragma unroll
        for (int i = 0; i < 8; i++) hs += sred[i];
        hrow[row] = hs * LN2F;
    }
}

// 16x16 pair tile per block, 128 threads (4 warps), each thread a 2x1 micro-tile
// (i rows ti, ti+8; one j).
// C(i,j) ~= ln2*(T1 - 2): the 2eps*T2 correction (~4.6e-5 per jsd) is COMMON-MODE
// across pairs and cancels in (diag mean - offdiag mean); residual ~2e-8 abs.
// Dropping T2 cuts the inner loop to FADD+MUFU+FFMA = 3 issues per lg2, making
// MUFU.LG2 the sole saturable floor.
// T1 split even/odd k (384-term fp32 accumulators) for accuracy.
__global__ void __launch_bounds__(NT) pair_kernel(float* __restrict__ out) {
    __shared__ float As[TI * PADF];
    __shared__ float Bs[TI * PADF];
    __shared__ float rt4[4], rd4[4];
    __shared__ bool  s_last;

    const int tid = threadIdx.x;
    const int ib = blockIdx.x & 31;   // 512/16 = 32 tiles per dim
    const int jb = blockIdx.x >> 5;
    const int ti = tid & 7;           // i rows: ti, ti+8
    const int tj = tid >> 3;          // j row: tj (0..15)

    const float4* gp1 = (const float4*)(g_P1 + ib * TI * DD);
    const float4* gp2 = (const float4*)(g_P2 + jb * TI * DD);

    // per pair (0 = row ti, 1 = row ti+8): T1 even/odd k accumulators
    float T1e0 = 0.f, T1o0 = 0.f, T1e1 = 0.f, T1o1 = 0.f;

    #pragma unroll 1
    for (int kb = 0; kb < DD / BK; kb++) {
        // stage 16 x 128 chunk of each matrix: 512 float4 each, 128 threads -> 4 apiece
        #pragma unroll
        for (int r = 0; r < 4; r++) {
            int idx = tid + r * NT;            // 0..511
            int row = idx >> 5;                // /32
            int c   = idx & 31;
            ((float4*)As)[row * PAD4 + c] = gp1[row * (DD / 4) + kb * (BK / 4) + c];
        }
        #pragma unroll
        for (int r = 0; r < 4; r++) {
            int idx = tid + r * NT;
            int row = idx >> 5;
            int c   = idx & 31;
            ((float4*)Bs)[row * PAD4 + c] = gp2[row * (DD / 4) + kb * (BK / 4) + c];
        }
        __syncthreads();

        const float4* a0p = (const float4*)(As + ti * PADF);
        const float4* a1p = (const float4*)(As + (ti + 8) * PADF);
        const float4* bp  = (const float4*)(Bs + tj * PADF);

        #pragma unroll 8
        for (int k = 0; k < BK / 4; k++) {
            float4 a0 = a0p[k], a1 = a1p[k];
            float4 b  = bp[k];

            #define PAIRSTEP(cx, P)                                 \
            {                                                       \
                float s0 = a0.cx + b.cx;  float u0 = flg2(s0);      \
                float s1 = a1.cx + b.cx;  float u1 = flg2(s1);      \
                T1##P##0 = fmaf(s0, u0, T1##P##0);                  \
                T1##P##1 = fmaf(s1, u1, T1##P##1);                  \
            }
            PAIRSTEP(x, e)
            PAIRSTEP(y, o)
            PAIRSTEP(z, e)
            PAIRSTEP(w, o)
            #undef PAIRSTEP
        }
        __syncthreads();
    }

    const int gi0 = ib * TI + ti,  gi1 = gi0 + 8;
    const int gj  = jb * TI + tj;

    const float h10 = g_H1[gi0], h11 = g_H1[gi1];
    const float h2j = g_H2[gj];

    // C ~= ln2*(T1 - 2); jsd = 0.5*(H1 + H2 - C)
    #define JSD(T1v, hi, hj) \
        (0.5f * ((hi) + (hj) - LN2F * ((T1v) - 2.0f)))
    float j0 = JSD(T1e0 + T1o0, h10, h2j);
    float j1 = JSD(T1e1 + T1o1, h11, h2j);
    #undef JSD

    float t = j0 + j1;
    float d = 0.f;
    if (gi0 == gj) d += j0;
    if (gi1 == gj) d += j1;

    const int w = tid >> 5, l = tid & 31;
    #pragma unroll
    for (int o = 16; o; o >>= 1) {
        t += __shfl_xor_sync(0xffffffffu, t, o);
        d += __shfl_xor_sync(0xffffffffu, d, o);
    }
    if (l == 0) { rt4[w] = t; rd4[w] = d; }
    __syncthreads();

    // Per-block partial + ticket (canonical threadFenceReduction pattern)
    if (tid == 0) {
        g_ptot[blockIdx.x] = (rt4[0] + rt4[1]) + (rt4[2] + rt4[3]);
        g_pdia[blockIdx.x] = (rd4[0] + rd4[1]) + (rd4[2] + rd4[3]);
        __threadfence();
        unsigned ticket = atomicAdd(&g_counter, 1u);
        s_last = (ticket == (unsigned)(gridDim.x - 1));
    }
    __syncthreads();

    if (s_last) {
        // Last block: reduce all NBLK partials in double precision.
        double dt = 0.0, dd_ = 0.0;
        for (int i = tid; i < NBLK; i += NT) {
            float pt = *(volatile float*)&g_ptot[i];
            float pd = *(volatile float*)&g_pdia[i];
            dt  += (double)pt;
            dd_ += (double)pd;
        }
        #pragma unroll
        for (int o = 16; o; o >>= 1) {
            dt  += __shfl_xor_sync(0xffffffffu, dt, o);
            dd_ += __shfl_xor_sync(0xffffffffu, dd_, o);
        }
        __shared__ double dtot[4], ddia[4];
        if (l == 0) { dtot[w] = dt; ddia[w] = dd_; }
        __syncthreads();
        if (tid == 0) {
            double tot  = (dtot[0] + dtot[1]) + (dtot[2] + dtot[3]);
            double dia_ = (ddia[0] + ddia[1]) + (ddia[2] + ddia[3]);
            double pos = dia_ / (double)NR;
            double neg = -(tot - dia_) / ((double)NR * NR - NR);
            out[0] = (float)(pos + (double)LAMBDF * neg);
            g_counter = 0;   // reset for next graph replay
        }
    }
}

extern "C" void kernel_launch(void* const* d_in, const int* in_sizes, int n_in,
                              void* d_out, int out_size) {
    const float* z1 = (const float*)d_in[0];
    const float* z2 = (const float*)d_in[1];
    float* out = (float*)d_out;

    softmax_kernel<<<2 * NR, 256>>>(z1, z2);
    pair_kernel<<<NBLK, NT>>>(out);
}

// round 10
// speedup vs baseline: 1.3186x; 1.0387x over previous
#include <cuda_runtime.h>

#define NR 512
#define DD 768
#define EPSF 1e-8f
#define LN2F 0.69314718055994530942f
#define LAMBDF 1.0f

#define TI 16                // pair tile is 16x16
#define BK 96                // k-chunk; 8 chunks; double-buffered smem = 25.6KB -> 8 blocks/SM
#define BK4 (BK/4)           // 24 float4 per row-chunk
#define PADF 100             // 96 + 4 floats: row*4 mod 32 banks -> conflict-free LDS.128
#define PAD4 (PADF/4)        // 25
#define NKB (DD/BK)          // 8
#define NBLK ((NR/TI)*(NR/TI))   // 1024 pair blocks
#define NT 128               // 4 warps -> all 4 SMSPs

// Raw MUFU.LG2/EX2, ftz (exact for our range s in [2e-8, 2]); avoids the
// non-ftz denormal fixup sequence (confirmed R6: alu 29%->0.8%).
__device__ __forceinline__ float flg2(float x) {
    float r;
    asm("lg2.approx.ftz.f32 %0, %1;" : "=f"(r) : "f"(x));
    return r;
}
__device__ __forceinline__ float fex2(float x) {
    float r;
    asm("ex2.approx.ftz.f32 %0, %1;" : "=f"(r) : "f"(x));
    return r;
}
__device__ __forceinline__ void cp16(unsigned dst, const void* src) {
    asm volatile("cp.async.cg.shared.global [%0], [%1], 16;" :: "r"(dst), "l"(src));
}

// Scratch (no cudaMalloc allowed)
__device__ float    g_P1[NR * DD];   // p1 + eps
__device__ float    g_P2[NR * DD];   // p2 + eps
__device__ float    g_H1[NR];        // sum p1*ln(p1+eps)
__device__ float    g_H2[NR];
__device__ float    g_ptot[NBLK];    // per-block tot partials
__device__ float    g_pdia[NBLK];    // per-block dia partials
__device__ unsigned g_counter = 0;   // ticket for last-block finalize (self-resetting)

// One block per row; blocks [0,512) -> z1, [512,1024) -> z2. 256 threads, 3 elems each.
__global__ void softmax_kernel(const float* __restrict__ z1,
                               const float* __restrict__ z2) {
    const int  row   = blockIdx.x & (NR - 1);
    const bool first = blockIdx.x < NR;
    const float* src = (first ? z1 : z2) + row * DD;
    float*       dst = (first ? g_P1 : g_P2) + row * DD;
    float*      hrow = first ? g_H1 : g_H2;

    const int tid = threadIdx.x;
    const int w = tid >> 5, l = tid & 31;

    float x0 = src[tid];
    float x1 = src[tid + 256];
    float x2 = src[tid + 512];

    __shared__ float sred[8];

    // --- max reduce ---
    float mx = fmaxf(x0, fmaxf(x1, x2));
    #pragma unroll
    for (int o = 16; o; o >>= 1) mx = fmaxf(mx, __shfl_xor_sync(0xffffffffu, mx, o));
    if (l == 0) sred[w] = mx;
    __syncthreads();
    mx = sred[0];
    #pragma unroll
    for (int i = 1; i < 8; i++) mx = fmaxf(mx, sred[i]);
    __syncthreads();

    // --- exp + sum reduce (exp(x) = ex2(x * log2 e)) ---
    const float L2E = 1.4426950408889634f;
    float e0 = fex2((x0 - mx) * L2E);
    float e1 = fex2((x1 - mx) * L2E);
    float e2 = fex2((x2 - mx) * L2E);
    float s = e0 + e1 + e2;
    #pragma unroll
    for (int o = 16; o; o >>= 1) s += __shfl_xor_sync(0xffffffffu, s, o);
    if (l == 0) sred[w] = s;
    __syncthreads();
    s = sred[0];
    #pragma unroll
    for (int i = 1; i < 8; i++) s += sred[i];
    __syncthreads();

    const float inv = 1.0f / s;
    float p0 = e0 * inv, p1 = e1 * inv, p2 = e2 * inv;
    float a0 = p0 + EPSF, a1 = p1 + EPSF, a2 = p2 + EPSF;
    dst[tid]       = a0;
    dst[tid + 256] = a1;
    dst[tid + 512] = a2;

    // --- H = sum p * ln(p+eps) ---
    float h = p0 * flg2(a0) + p1 * flg2(a1) + p2 * flg2(a2);
    #pragma unroll
    for (int o = 16; o; o >>= 1) h += __shfl_xor_sync(0xffffffffu, h, o);
    if (l == 0) sred[w] = h;
    __syncthreads();
    if (tid == 0) {
        float hs = 0.f;
        #pragma unroll
        for (int i = 0; i < 8; i++) hs += sred[i];
        hrow[row] = hs * LN2F;
    }
}

// 16x16 pair tile per block, 128 threads (4 warps), each thread a 2x1 micro-tile
// (i rows ti, ti+8; one j). cp.async double-buffered k-pipeline: next chunk's
// gmem loads overlap the current chunk's compute, removing the load bubbles
// that held MUFU at 77% (R9). MUFU.LG2 is the sole floor.
// C(i,j) ~= ln2*(T1 - 2): 2eps*T2 correction is common-mode, cancels in
// pos-neg (residual ~2e-8 abs). T1 split even/odd k for accuracy.
__global__ void __launch_bounds__(NT) pair_kernel(float* __restrict__ out) {
    __shared__ float As[2][TI * PADF];
    __shared__ float Bs[2][TI * PADF];
    __shared__ float rt4[4], rd4[4];
    __shared__ bool  s_last;

    const int tid = threadIdx.x;
    const int ib = blockIdx.x & 31;   // 512/16 = 32 tiles per dim
    const int jb = blockIdx.x >> 5;
    const int ti = tid & 7;           // i rows: ti, ti+8
    const int tj = tid >> 3;          // j row: tj (0..15)

    const float4* gp1 = (const float4*)(g_P1 + ib * TI * DD);
    const float4* gp2 = (const float4*)(g_P2 + jb * TI * DD);

    // Per-thread load slots: 3 float4 per matrix per chunk (384 = 128*3)
    int lrow[3], lcol[3];
    #pragma unroll
    for (int r = 0; r < 3; r++) {
        int idx = tid + r * NT;
        lrow[r] = idx / BK4;
        lcol[r] = idx % BK4;
    }

    #define ISSUE_LOAD(kb, buf)                                                 \
    {                                                                           \
        _Pragma("unroll")                                                       \
        for (int r = 0; r < 3; r++) {                                           \
            int go = lrow[r] * (DD / 4) + (kb) * BK4 + lcol[r];                 \
            unsigned sa = (unsigned)__cvta_generic_to_shared(                   \
                &As[buf][lrow[r] * PADF + lcol[r] * 4]);                        \
            unsigned sb = (unsigned)__cvta_generic_to_shared(                   \
                &Bs[buf][lrow[r] * PADF + lcol[r] * 4]);                        \
            cp16(sa, gp1 + go);                                                 \
            cp16(sb, gp2 + go);                                                 \
        }                                                                       \
        asm volatile("cp.async.commit_group;");                                 \
    }

    // per pair (0 = row ti, 1 = row ti+8): T1 even/odd k accumulators
    float T1e0 = 0.f, T1o0 = 0.f, T1e1 = 0.f, T1o1 = 0.f;

    ISSUE_LOAD(0, 0);

    #pragma unroll 1
    for (int kb = 0; kb < NKB; kb++) {
        const int buf = kb & 1;
        if (kb + 1 < NKB) {
            ISSUE_LOAD(kb + 1, buf ^ 1);
            asm volatile("cp.async.wait_group 1;");
        } else {
            asm volatile("cp.async.wait_group 0;");
        }
        __syncthreads();

        const float4* a0p = (const float4*)(As[buf] + ti * PADF);
        const float4* a1p = (const float4*)(As[buf] + (ti + 8) * PADF);
        const float4* bp  = (const float4*)(Bs[buf] + tj * PADF);

        #pragma unroll 8
        for (int k = 0; k < BK4; k++) {
            float4 a0 = a0p[k], a1 = a1p[k];
            float4 b  = bp[k];

            #define PAIRSTEP(cx, P)                                 \
            {                                                       \
                float s0 = a0.cx + b.cx;  float u0 = flg2(s0);      \
                float s1 = a1.cx + b.cx;  float u1 = flg2(s1);      \
                T1##P##0 = fmaf(s0, u0, T1##P##0);                  \
                T1##P##1 = fmaf(s1, u1, T1##P##1);                  \
            }
            PAIRSTEP(x, e)
            PAIRSTEP(y, o)
            PAIRSTEP(z, e)
            PAIRSTEP(w, o)
            #undef PAIRSTEP
        }
        __syncthreads();   // orders last reads of buf before it is overwritten
    }
    #undef ISSUE_LOAD

    const int gi0 = ib * TI + ti,  gi1 = gi0 + 8;
    const int gj  = jb * TI + tj;

    const float h10 = g_H1[gi0], h11 = g_H1[gi1];
    const float h2j = g_H2[gj];

    // C ~= ln2*(T1 - 2); jsd = 0.5*(H1 + H2 - C)
    #define JSD(T1v, hi, hj) \
        (0.5f * ((hi) + (hj) - LN2F * ((T1v) - 2.0f)))
    float j0 = JSD(T1e0 + T1o0, h10, h2j);
    float j1 = JSD(T1e1 + T1o1, h11, h2j);
    #undef JSD

    float t = j0 + j1;
    float d = 0.f;
    if (gi0 == gj) d += j0;
    if (gi1 == gj) d += j1;

    const int w = tid >> 5, l = tid & 31;
    #pragma unroll
    for (int o = 16; o; o >>= 1) {
        t += __shfl_xor_sync(0xffffffffu, t, o);
        d += __shfl_xor_sync(0xffffffffu, d, o);
    }
    if (l == 0) { rt4[w] = t; rd4[w] = d; }
    __syncthreads();

    // Per-block partial + ticket (canonical threadFenceReduction pattern)
    if (tid == 0) {
        g_ptot[blockIdx.x] = (rt4[0] + rt4[1]) + (rt4[2] + rt4[3]);
        g_pdia[blockIdx.x] = (rd4[0] + rd4[1]) + (rd4[2] + rd4[3]);
        __threadfence();
        unsigned ticket = atomicAdd(&g_counter, 1u);
        s_last = (ticket == (unsigned)(gridDim.x - 1));
    }
    __syncthreads();

    if (s_last) {
        // Last block: reduce all NBLK partials in double precision.
        double dt = 0.0, dd_ = 0.0;
        for (int i = tid; i < NBLK; i += NT) {
            float pt = *(volatile float*)&g_ptot[i];
            float pd = *(volatile float*)&g_pdia[i];
            dt  += (double)pt;
            dd_ += (double)pd;
        }
        #pragma unroll
        for (int o = 16; o; o >>= 1) {
            dt  += __shfl_xor_sync(0xffffffffu, dt, o);
            dd_ += __shfl_xor_sync(0xffffffffu, dd_, o);
        }
        __shared__ double dtot[4], ddia[4];
        if (l == 0) { dtot[w] = dt; ddia[w] = dd_; }
        __syncthreads();
        if (tid == 0) {
            double tot  = (dtot[0] + dtot[1]) + (dtot[2] + dtot[3]);
            double dia_ = (ddia[0] + ddia[1]) + (ddia[2] + ddia[3]);
            double pos = dia_ / (double)NR;
            double neg = -(tot - dia_) / ((double)NR * NR - NR);
            out[0] = (float)(pos + (double)LAMBDF * neg);
            g_counter = 0;   // reset for next graph replay
        }
    }
}

extern "C" void kernel_launch(void* const* d_in, const int* in_sizes, int n_in,
                              void* d_out, int out_size) {
    const float* z1 = (const float*)d_in[0];
    const float* z2 = (const float*)d_in[1];
    float* out = (float*)d_out;

    softmax_kernel<<<2 * NR, 256>>>(z1, z2);
    pair_kernel<<<NBLK, NT>>>(out);
}

// round 13
// speedup vs baseline: 1.3678x; 1.0373x over previous
#include <cuda_runtime.h>

#define NR 512
#define DD 768
#define EPSF 1e-8f
#define LN2F 0.69314718055994530942f
#define LAMBDF 1.0f

#define TI 16                // pair tile is 16x16
#define BK 96                // k-chunk; 8 chunks; double-buffered smem
#define BK4 (BK/4)           // 24 float4 per row-chunk
#define PADF 100             // 96 + 4 floats: conflict-free LDS.128
#define PAD4 (PADF/4)        // 25
#define NKB (DD/BK)          // 8
#define NBLK ((NR/TI)*(NR/TI))   // 1024 pair blocks
#define NT 128               // 4 warps -> all 4 SMSPs

// Raw MUFU.LG2/EX2, ftz (exact for our range s in [2e-8, 2]).
__device__ __forceinline__ float flg2(float x) {
    float r;
    asm("lg2.approx.ftz.f32 %0, %1;" : "=f"(r) : "f"(x));
    return r;
}
__device__ __forceinline__ float fex2(float x) {
    float r;
    asm("ex2.approx.ftz.f32 %0, %1;" : "=f"(r) : "f"(x));
    return r;
}
__device__ __forceinline__ void cp16(unsigned dst, const void* src) {
    asm volatile("cp.async.cg.shared.global [%0], [%1], 16;" :: "r"(dst), "l"(src));
}

// Polynomial log2 on the FMA/ALU pipes (offloads the saturated MUFU pipe).
// s normal positive. Normalize mantissa to [2/3, 4/3): if mant >= mant(4/3),
// treat m' = m/2 and bump exponent. Then exact Taylor deg-8 of lg2(1+t),
// |t| <= 1/3 -> |err| <= 8.1e-6 abs. Coeffs are (+/-)(1/ln2)/k — exact series.
__device__ __forceinline__ float plg2(float s) {
    int   vx   = __float_as_int(s);
    int   mant = vx & 0x007FFFFF;
    bool  big  = mant >= 0x2AAAAB;                 // m >= 4/3
    int   eb   = big ? (vx + 0x00800000) : vx;     // round exponent up
    float ef   = (float)((eb >> 23) - 127);
    float m    = __int_as_float(mant | (big ? 0x3F000000 : 0x3F800000));
    float t    = m - 1.0f;                          // in [-1/3, 1/3)
    float q;
    q = fmaf(-0.18033688f, t,  0.20609929f);
    q = fmaf(q, t, -0.24044917f);
    q = fmaf(q, t,  0.28853901f);
    q = fmaf(q, t, -0.36067376f);
    q = fmaf(q, t,  0.48089835f);
    q = fmaf(q, t, -0.72134752f);
    q = fmaf(q, t,  1.44269504f);
    return fmaf(t, q, ef);
}

// Scratch (no cudaMalloc allowed)
__device__ float    g_P1[NR * DD];   // p1 + eps
__device__ float    g_P2[NR * DD];   // p2 + eps
__device__ float    g_H1[NR];        // sum p1*ln(p1+eps)
__device__ float    g_H2[NR];
__device__ float    g_ptot[NBLK];    // per-block tot partials
__device__ float    g_pdia[NBLK];    // per-block dia partials
__device__ unsigned g_counter = 0;   // ticket for last-block finalize (self-resetting)

// One block per row; blocks [0,512) -> z1, [512,1024) -> z2. 256 threads, 3 elems each.
__global__ void softmax_kernel(const float* __restrict__ z1,
                               const float* __restrict__ z2) {
    const int  row   = blockIdx.x & (NR - 1);
    const bool first = blockIdx.x < NR;
    const float* src = (first ? z1 : z2) + row * DD;
    float*       dst = (first ? g_P1 : g_P2) + row * DD;
    float*      hrow = first ? g_H1 : g_H2;

    const int tid = threadIdx.x;
    const int w = tid >> 5, l = tid & 31;

    float x0 = src[tid];
    float x1 = src[tid + 256];
    float x2 = src[tid + 512];

    __shared__ float sred[8];

    float mx = fmaxf(x0, fmaxf(x1, x2));
    #pragma unroll
    for (int o = 16; o; o >>= 1) mx = fmaxf(mx, __shfl_xor_sync(0xffffffffu, mx, o));
    if (l == 0) sred[w] = mx;
    __syncthreads();
    mx = sred[0];
    #pragma unroll
    for (int i = 1; i < 8; i++) mx = fmaxf(mx, sred[i]);
    __syncthreads();

    const float L2E = 1.4426950408889634f;
    float e0 = fex2((x0 - mx) * L2E);
    float e1 = fex2((x1 - mx) * L2E);
    float e2 = fex2((x2 - mx) * L2E);
    float s = e0 + e1 + e2;
    #pragma unroll
    for (int o = 16; o; o >>= 1) s += __shfl_xor_sync(0xffffffffu, s, o);
    if (l == 0) sred[w] = s;
    __syncthreads();
    s = sred[0];
    #pragma unroll
    for (int i = 1; i < 8; i++) s += sred[i];
    __syncthreads();

    const float inv = 1.0f / s;
    float p0 = e0 * inv, p1 = e1 * inv, p2 = e2 * inv;
    float a0 = p0 + EPSF, a1 = p1 + EPSF, a2 = p2 + EPSF;
    dst[tid]       = a0;
    dst[tid + 256] = a1;
    dst[tid + 512] = a2;

    float h = p0 * flg2(a0) + p1 * flg2(a1) + p2 * flg2(a2);
    #pragma unroll
    for (int o = 16; o; o >>= 1) h += __shfl_xor_sync(0xffffffffu, h, o);
    if (l == 0) sred[w] = h;
    __syncthreads();
    if (tid == 0) {
        float hs = 0.f;
        #pragma unroll
        for (int i = 0; i < 8; i++) hs += sred[i];
        hrow[row] = hs * LN2F;
    }
}

// 16x16 pair tile per block, 128 threads (4 warps), each thread a 2x1 micro-tile.
// cp.async double-buffered k-pipeline. Of the 8 lg2 per float4-quad, 7 go to
// MUFU and 1 to the polynomial path on the otherwise-idle FMA pipe, cutting
// the binding MUFU floor by 12.5%.
__global__ void __launch_bounds__(NT, 7) pair_kernel(float* __restrict__ out) {
    __shared__ float As[2][TI * PADF];
    __shared__ float Bs[2][TI * PADF];
    __shared__ float rt4[4], rd4[4];
    __shared__ bool  s_last;

    const int tid = threadIdx.x;
    const int ib = blockIdx.x & 31;   // 512/16 = 32 tiles per dim
    const int jb = blockIdx.x >> 5;
    const int ti = tid & 7;           // i rows: ti, ti+8
    const int tj = tid >> 3;          // j row: tj (0..15)

    const float4* gp1 = (const float4*)(g_P1 + ib * TI * DD);
    const float4* gp2 = (const float4*)(g_P2 + jb * TI * DD);

    int lrow[3], lcol[3];
    #pragma unroll
    for (int r = 0; r < 3; r++) {
        int idx = tid + r * NT;
        lrow[r] = idx / BK4;
        lcol[r] = idx % BK4;
    }

    #define ISSUE_LOAD(kb, buf)                                                 \
    {                                                                           \
        _Pragma("unroll")                                                       \
        for (int r = 0; r < 3; r++) {                                           \
            int go = lrow[r] * (DD / 4) + (kb) * BK4 + lcol[r];                 \
            unsigned sa = (unsigned)__cvta_generic_to_shared(                   \
                &As[buf][lrow[r] * PADF + lcol[r] * 4]);                        \
            unsigned sb = (unsigned)__cvta_generic_to_shared(                   \
                &Bs[buf][lrow[r] * PADF + lcol[r] * 4]);                        \
            cp16(sa, gp1 + go);                                                 \
            cp16(sb, gp2 + go);                                                 \
        }                                                                       \
        asm volatile("cp.async.commit_group;");                                 \
    }

    // per pair (0 = row ti, 1 = row ti+8): T1 even/odd k accumulators
    float T1e0 = 0.f, T1o0 = 0.f, T1e1 = 0.f, T1o1 = 0.f;

    ISSUE_LOAD(0, 0);

    #pragma unroll 1
    for (int kb = 0; kb < NKB; kb++) {
        const int buf = kb & 1;
        if (kb + 1 < NKB) {
            ISSUE_LOAD(kb + 1, buf ^ 1);
            asm volatile("cp.async.wait_group 1;");
        } else {
            asm volatile("cp.async.wait_group 0;");
        }
        __syncthreads();

        const float4* a0p = (const float4*)(As[buf] + ti * PADF);
        const float4* a1p = (const float4*)(As[buf] + (ti + 8) * PADF);
        const float4* bp  = (const float4*)(Bs[buf] + tj * PADF);

        #pragma unroll 8
        for (int k = 0; k < BK4; k++) {
            float4 a0 = a0p[k], a1 = a1p[k];
            float4 b  = bp[k];

            // row 0 (ti): all 4 via MUFU
            {
                float s0 = a0.x + b.x;  float u0 = flg2(s0);
                float s1 = a0.y + b.y;  float u1 = flg2(s1);
                float s2 = a0.z + b.z;  float u2 = flg2(s2);
                float s3 = a0.w + b.w;  float u3 = flg2(s3);
                T1e0 = fmaf(s0, u0, T1e0);
                T1o0 = fmaf(s1, u1, T1o0);
                T1e0 = fmaf(s2, u2, T1e0);
                T1o0 = fmaf(s3, u3, T1o0);
            }
            // row 1 (ti+8): x,y,z via MUFU, w via FMA-pipe polynomial
            {
                float s0 = a1.x + b.x;  float u0 = flg2(s0);
                float s1 = a1.y + b.y;  float u1 = flg2(s1);
                float s2 = a1.z + b.z;  float u2 = flg2(s2);
                float s3 = a1.w + b.w;  float u3 = plg2(s3);
                T1e1 = fmaf(s0, u0, T1e1);
                T1o1 = fmaf(s1, u1, T1o1);
                T1e1 = fmaf(s2, u2, T1e1);
                T1o1 = fmaf(s3, u3, T1o1);
            }
        }
        __syncthreads();   // orders last reads of buf before it is overwritten
    }
    #undef ISSUE_LOAD

    const int gi0 = ib * TI + ti,  gi1 = gi0 + 8;
    const int gj  = jb * TI + tj;

    const float h10 = g_H1[gi0], h11 = g_H1[gi1];
    const float h2j = g_H2[gj];

    // C ~= ln2*(T1 - 2); jsd = 0.5*(H1 + H2 - C); eps correction is
    // common-mode and cancels in pos-neg (residual ~2e-8 abs).
    #define JSD(T1v, hi, hj) \
        (0.5f * ((hi) + (hj) - LN2F * ((T1v) - 2.0f)))
    float j0 = JSD(T1e0 + T1o0, h10, h2j);
    float j1 = JSD(T1e1 + T1o1, h11, h2j);
    #undef JSD

    float t = j0 + j1;
    float d = 0.f;
    if (gi0 == gj) d += j0;
    if (gi1 == gj) d += j1;

    const int w = tid >> 5, l = tid & 31;
    #pragma unroll
    for (int o = 16; o; o >>= 1) {
        t += __shfl_xor_sync(0xffffffffu, t, o);
        d += __shfl_xor_sync(0xffffffffu, d, o);
    }
    if (l == 0) { rt4[w] = t; rd4[w] = d; }
    __syncthreads();

    if (tid == 0) {
        g_ptot[blockIdx.x] = (rt4[0] + rt4[1]) + (rt4[2] + rt4[3]);
        g_pdia[blockIdx.x] = (rd4[0] + rd4[1]) + (rd4[2] + rd4[3]);
        __threadfence();
        unsigned ticket = atomicAdd(&g_counter, 1u);
        s_last = (ticket == (unsigned)(gridDim.x - 1));
    }
    __syncthreads();

    if (s_last) {
        double dt = 0.0, dd_ = 0.0;
        #pragma unroll
        for (int i = tid; i < NBLK; i += NT) {
            float pt = *(volatile float*)&g_ptot[i];
            float pd = *(volatile float*)&g_pdia[i];
            dt  += (double)pt;
            dd_ += (double)pd;
        }
        #pragma unroll
        for (int o = 16; o; o >>= 1) {
            dt  += __shfl_xor_sync(0xffffffffu, dt, o);
            dd_ += __shfl_xor_sync(0xffffffffu, dd_, o);
        }
        __shared__ double dtot[4], ddia[4];
        if (l == 0) { dtot[w] = dt; ddia[w] = dd_; }
        __syncthreads();
        if (tid == 0) {
            double tot  = (dtot[0] + dtot[1]) + (dtot[2] + dtot[3]);
            double dia_ = (ddia[0] + ddia[1]) + (ddia[2] + ddia[3]);
            double pos = dia_ / (double)NR;
            double neg = -(tot - dia_) / ((double)NR * NR - NR);
            out[0] = (float)(pos + (double)LAMBDF * neg);
            g_counter = 0;   // reset for next graph replay
        }
    }
}

extern "C" void kernel_launch(void* const* d_in, const int* in_sizes, int n_in,
                              void* d_out, int out_size) {
    const float* z1 = (const float*)d_in[0];
    const float* z2 = (const float*)d_in[1];
    float* out = (float*)d_out;

    softmax_kernel<<<2 * NR, 256>>>(z1, z2);
    pair_kernel<<<NBLK, NT>>>(out);
}

// round 14
// speedup vs baseline: 1.3685x; 1.0006x over previous
#include <cuda_runtime.h>

#define NR 512
#define DD 768
#define EPSF 1e-8f
#define LN2F 0.69314718055994530942f
#define LAMBDF 1.0f

#define TI 16                // pair tile is 16x16
#define BK 96                // k-chunk; 8 chunks; double-buffered smem
#define BK4 (BK/4)           // 24 float4 per row-chunk
#define PADF 100             // 96 + 4 floats: conflict-free LDS.128
#define PAD4 (PADF/4)        // 25
#define NKB (DD/BK)          // 8
#define NBLK ((NR/TI)*(NR/TI))   // 1024 pair blocks
#define NT 128               // 4 warps -> all 4 SMSPs

// Raw MUFU.LG2/EX2, ftz (exact for our range s in [2e-8, 2]).
__device__ __forceinline__ float flg2(float x) {
    float r;
    asm("lg2.approx.ftz.f32 %0, %1;" : "=f"(r) : "f"(x));
    return r;
}
__device__ __forceinline__ float fex2(float x) {
    float r;
    asm("ex2.approx.ftz.f32 %0, %1;" : "=f"(r) : "f"(x));
    return r;
}
__device__ __forceinline__ void cp16(unsigned dst, const void* src) {
    asm volatile("cp.async.cg.shared.global [%0], [%1], 16;" :: "r"(dst), "l"(src));
}

// Polynomial log2 on the FMA/ALU pipes (offloads the saturated MUFU pipe).
// s normal positive. Normalize mantissa to [2/3, 4/3): if mant >= mant(4/3),
// treat m' = m/2 and bump exponent. Then exact Taylor deg-8 of lg2(1+t),
// |t| <= 1/3 -> |err| <= 8.1e-6 abs. Coeffs are (+/-)(1/ln2)/k — exact series.
__device__ __forceinline__ float plg2(float s) {
    int   vx   = __float_as_int(s);
    int   mant = vx & 0x007FFFFF;
    bool  big  = mant >= 0x2AAAAB;                 // m >= 4/3
    int   eb   = big ? (vx + 0x00800000) : vx;     // round exponent up
    float ef   = (float)((eb >> 23) - 127);
    float m    = __int_as_float(mant | (big ? 0x3F000000 : 0x3F800000));
    float t    = m - 1.0f;                          // in [-1/3, 1/3)
    float q;
    q = fmaf(-0.18033688f, t,  0.20609929f);
    q = fmaf(q, t, -0.24044917f);
    q = fmaf(q, t,  0.28853901f);
    q = fmaf(q, t, -0.36067376f);
    q = fmaf(q, t,  0.48089835f);
    q = fmaf(q, t, -0.72134752f);
    q = fmaf(q, t,  1.44269504f);
    return fmaf(t, q, ef);
}

// Scratch (no cudaMalloc allowed)
__device__ float    g_P1[NR * DD];   // p1 + eps
__device__ float    g_P2[NR * DD];   // p2 + eps
__device__ float    g_H1[NR];        // sum p1*ln(p1+eps)
__device__ float    g_H2[NR];
__device__ float    g_ptot[NBLK];    // per-block tot partials
__device__ float    g_pdia[NBLK];    // per-block dia partials
__device__ unsigned g_counter = 0;   // ticket for last-block finalize (self-resetting)

// One block per row; blocks [0,512) -> z1, [512,1024) -> z2. 256 threads, 3 elems each.
__global__ void softmax_kernel(const float* __restrict__ z1,
                               const float* __restrict__ z2) {
    const int  row   = blockIdx.x & (NR - 1);
    const bool first = blockIdx.x < NR;
    const float* src = (first ? z1 : z2) + row * DD;
    float*       dst = (first ? g_P1 : g_P2) + row * DD;
    float*      hrow = first ? g_H1 : g_H2;

    const int tid = threadIdx.x;
    const int w = tid >> 5, l = tid & 31;

    float x0 = src[tid];
    float x1 = src[tid + 256];
    float x2 = src[tid + 512];

    __shared__ float sred[8];

    float mx = fmaxf(x0, fmaxf(x1, x2));
    #pragma unroll
    for (int o = 16; o; o >>= 1) mx = fmaxf(mx, __shfl_xor_sync(0xffffffffu, mx, o));
    if (l == 0) sred[w] = mx;
    __syncthreads();
    mx = sred[0];
    #pragma unroll
    for (int i = 1; i < 8; i++) mx = fmaxf(mx, sred[i]);
    __syncthreads();

    const float L2E = 1.4426950408889634f;
    float e0 = fex2((x0 - mx) * L2E);
    float e1 = fex2((x1 - mx) * L2E);
    float e2 = fex2((x2 - mx) * L2E);
    float s = e0 + e1 + e2;
    #pragma unroll
    for (int o = 16; o; o >>= 1) s += __shfl_xor_sync(0xffffffffu, s, o);
    if (l == 0) sred[w] = s;
    __syncthreads();
    s = sred[0];
    #pragma unroll
    for (int i = 1; i < 8; i++) s += sred[i];
    __syncthreads();

    const float inv = 1.0f / s;
    float p0 = e0 * inv, p1 = e1 * inv, p2 = e2 * inv;
    float a0 = p0 + EPSF, a1 = p1 + EPSF, a2 = p2 + EPSF;
    dst[tid]       = a0;
    dst[tid + 256] = a1;
    dst[tid + 512] = a2;

    float h = p0 * flg2(a0) + p1 * flg2(a1) + p2 * flg2(a2);
    #pragma unroll
    for (int o = 16; o; o >>= 1) h += __shfl_xor_sync(0xffffffffu, h, o);
    if (l == 0) sred[w] = h;
    __syncthreads();
    if (tid == 0) {
        float hs = 0.f;
        #pragma unroll
        for (int i = 0; i < 8; i++) hs += sred[i];
        hrow[row] = hs * LN2F;
    }
}

// 16x16 pair tile per block, 128 threads (4 warps), each thread a 2x1 micro-tile.
// cp.async double-buffered k-pipeline. Of the 8 lg2 per float4-quad, 7 go to
// MUFU and 1 to the polynomial path on the otherwise-idle FMA pipe, cutting
// the binding MUFU floor by 12.5%.
__global__ void __launch_bounds__(NT, 7) pair_kernel(float* __restrict__ out) {
    __shared__ float As[2][TI * PADF];
    __shared__ float Bs[2][TI * PADF];
    __shared__ float rt4[4], rd4[4];
    __shared__ bool  s_last;

    const int tid = threadIdx.x;
    const int ib = blockIdx.x & 31;   // 512/16 = 32 tiles per dim
    const int jb = blockIdx.x >> 5;
    const int ti = tid & 7;           // i rows: ti, ti+8
    const int tj = tid >> 3;          // j row: tj (0..15)

    const float4* gp1 = (const float4*)(g_P1 + ib * TI * DD);
    const float4* gp2 = (const float4*)(g_P2 + jb * TI * DD);

    int lrow[3], lcol[3];
    #pragma unroll
    for (int r = 0; r < 3; r++) {
        int idx = tid + r * NT;
        lrow[r] = idx / BK4;
        lcol[r] = idx % BK4;
    }

    #define ISSUE_LOAD(kb, buf)                                                 \
    {                                                                           \
        _Pragma("unroll")                                                       \
        for (int r = 0; r < 3; r++) {                                           \
            int go = lrow[r] * (DD / 4) + (kb) * BK4 + lcol[r];                 \
            unsigned sa = (unsigned)__cvta_generic_to_shared(                   \
                &As[buf][lrow[r] * PADF + lcol[r] * 4]);                        \
            unsigned sb = (unsigned)__cvta_generic_to_shared(                   \
                &Bs[buf][lrow[r] * PADF + lcol[r] * 4]);                        \
            cp16(sa, gp1 + go);                                                 \
            cp16(sb, gp2 + go);                                                 \
        }                                                                       \
        asm volatile("cp.async.commit_group;");                                 \
    }

    // per pair (0 = row ti, 1 = row ti+8): T1 even/odd k accumulators
    float T1e0 = 0.f, T1o0 = 0.f, T1e1 = 0.f, T1o1 = 0.f;

    ISSUE_LOAD(0, 0);

    #pragma unroll 1
    for (int kb = 0; kb < NKB; kb++) {
        const int buf = kb & 1;
        if (kb + 1 < NKB) {
            ISSUE_LOAD(kb + 1, buf ^ 1);
            asm volatile("cp.async.wait_group 1;");
        } else {
            asm volatile("cp.async.wait_group 0;");
        }
        __syncthreads();

        const float4* a0p = (const float4*)(As[buf] + ti * PADF);
        const float4* a1p = (const float4*)(As[buf] + (ti + 8) * PADF);
        const float4* bp  = (const float4*)(Bs[buf] + tj * PADF);

        #pragma unroll 8
        for (int k = 0; k < BK4; k++) {
            float4 a0 = a0p[k], a1 = a1p[k];
            float4 b  = bp[k];

            // row 0 (ti): all 4 via MUFU
            {
                float s0 = a0.x + b.x;  float u0 = flg2(s0);
                float s1 = a0.y + b.y;  float u1 = flg2(s1);
                float s2 = a0.z + b.z;  float u2 = flg2(s2);
                float s3 = a0.w + b.w;  float u3 = flg2(s3);
                T1e0 = fmaf(s0, u0, T1e0);
                T1o0 = fmaf(s1, u1, T1o0);
                T1e0 = fmaf(s2, u2, T1e0);
                T1o0 = fmaf(s3, u3, T1o0);
            }
            // row 1 (ti+8): x,y,z via MUFU, w via FMA-pipe polynomial
            {
                float s0 = a1.x + b.x;  float u0 = flg2(s0);
                float s1 = a1.y + b.y;  float u1 = flg2(s1);
                float s2 = a1.z + b.z;  float u2 = flg2(s2);
                float s3 = a1.w + b.w;  float u3 = plg2(s3);
                T1e1 = fmaf(s0, u0, T1e1);
                T1o1 = fmaf(s1, u1, T1o1);
                T1e1 = fmaf(s2, u2, T1e1);
                T1o1 = fmaf(s3, u3, T1o1);
            }
        }
        __syncthreads();   // orders last reads of buf before it is overwritten
    }
    #undef ISSUE_LOAD

    const int gi0 = ib * TI + ti,  gi1 = gi0 + 8;
    const int gj  = jb * TI + tj;

    const float h10 = g_H1[gi0], h11 = g_H1[gi1];
    const float h2j = g_H2[gj];

    // C ~= ln2*(T1 - 2); jsd = 0.5*(H1 + H2 - C); eps correction is
    // common-mode and cancels in pos-neg (residual ~2e-8 abs).
    #define JSD(T1v, hi, hj) \
        (0.5f * ((hi) + (hj) - LN2F * ((T1v) - 2.0f)))
    float j0 = JSD(T1e0 + T1o0, h10, h2j);
    float j1 = JSD(T1e1 + T1o1, h11, h2j);
    #undef JSD

    float t = j0 + j1;
    float d = 0.f;
    if (gi0 == gj) d += j0;
    if (gi1 == gj) d += j1;

    const int w = tid >> 5, l = tid & 31;
    #pragma unroll
    for (int o = 16; o; o >>= 1) {
        t += __shfl_xor_sync(0xffffffffu, t, o);
        d += __shfl_xor_sync(0xffffffffu, d, o);
    }
    if (l == 0) { rt4[w] = t; rd4[w] = d; }
    __syncthreads();

    if (tid == 0) {
        g_ptot[blockIdx.x] = (rt4[0] + rt4[1]) + (rt4[2] + rt4[3]);
        g_pdia[blockIdx.x] = (rd4[0] + rd4[1]) + (rd4[2] + rd4[3]);
        __threadfence();
        unsigned ticket = atomicAdd(&g_counter, 1u);
        s_last = (ticket == (unsigned)(gridDim.x - 1));
    }
    __syncthreads();

    if (s_last) {
        double dt = 0.0, dd_ = 0.0;
        #pragma unroll
        for (int i = tid; i < NBLK; i += NT) {
            float pt = *(volatile float*)&g_ptot[i];
            float pd = *(volatile float*)&g_pdia[i];
            dt  += (double)pt;
            dd_ += (double)pd;
        }
        #pragma unroll
        for (int o = 16; o; o >>= 1) {
            dt  += __shfl_xor_sync(0xffffffffu, dt, o);
            dd_ += __shfl_xor_sync(0xffffffffu, dd_, o);
        }
        __shared__ double dtot[4], ddia[4];
        if (l == 0) { dtot[w] = dt; ddia[w] = dd_; }
        __syncthreads();
        if (tid == 0) {
            double tot  = (dtot[0] + dtot[1]) + (dtot[2] + dtot[3]);
            double dia_ = (ddia[0] + ddia[1]) + (ddia[2] + ddia[3]);
            double pos = dia_ / (double)NR;
            double neg = -(tot - dia_) / ((double)NR * NR - NR);
            out[0] = (float)(pos + (double)LAMBDF * neg);
            g_counter = 0;   // reset for next graph replay
        }
    }
}

extern "C" void kernel_launch(void* const* d_in, const int* in_sizes, int n_in,
                              void* d_out, int out_size) {
    const float* z1 = (const float*)d_in[0];
    const float* z2 = (const float*)d_in[1];
    float* out = (float*)d_out;

    softmax_kernel<<<2 * NR, 256>>>(z1, z2);
    pair_kernel<<<NBLK, NT>>>(out);
}

// round 15
// speedup vs baseline: 1.4148x; 1.0338x over previous
#include <cuda_runtime.h>

#define NR 512
#define DD 768
#define EPSF 1e-8f
#define LN2F 0.69314718055994530942f
#define LAMBDF 1.0f

#define TI 16                // pair tile is 16x16
#define BK 64                // k-chunk; 12 chunks; double-buffered smem = 17.4KB -> 7 blocks/SM
#define BK4 (BK/4)           // 16 float4 per row-chunk
#define PADF 68              // 64 + 4 floats: stride 17 float4 (odd) -> conflict-free LDS.128
#define PAD4 (PADF/4)        // 17
#define NKB (DD/BK)          // 12
#define NBLK ((NR/TI)*(NR/TI))   // 1024 pair blocks; 148 SMs x 7 = 1036 -> single wave
#define NT 128               // 4 warps -> all 4 SMSPs

// Raw MUFU.LG2/EX2, ftz (exact for our range s in [2e-8, 2]).
__device__ __forceinline__ float flg2(float x) {
    float r;
    asm("lg2.approx.ftz.f32 %0, %1;" : "=f"(r) : "f"(x));
    return r;
}
__device__ __forceinline__ float fex2(float x) {
    float r;
    asm("ex2.approx.ftz.f32 %0, %1;" : "=f"(r) : "f"(x));
    return r;
}
__device__ __forceinline__ void cp16(unsigned dst, const void* src) {
    asm volatile("cp.async.cg.shared.global [%0], [%1], 16;" :: "r"(dst), "l"(src));
}

// Polynomial log2 on the FMA/ALU pipes (offloads the saturated MUFU pipe).
// Normalize mantissa to [2/3, 4/3), then exact Taylor deg-8 of lg2(1+t),
// |t| <= 1/3 -> |err| <= 8.1e-6 abs. Coeffs are (+/-)(1/ln2)/k — exact series.
__device__ __forceinline__ float plg2(float s) {
    int   vx   = __float_as_int(s);
    int   mant = vx & 0x007FFFFF;
    bool  big  = mant >= 0x2AAAAB;                 // m >= 4/3
    int   eb   = big ? (vx + 0x00800000) : vx;     // round exponent up
    float ef   = (float)((eb >> 23) - 127);
    float m    = __int_as_float(mant | (big ? 0x3F000000 : 0x3F800000));
    float t    = m - 1.0f;                          // in [-1/3, 1/3)
    float q;
    q = fmaf(-0.18033688f, t,  0.20609929f);
    q = fmaf(q, t, -0.24044917f);
    q = fmaf(q, t,  0.28853901f);
    q = fmaf(q, t, -0.36067376f);
    q = fmaf(q, t,  0.48089835f);
    q = fmaf(q, t, -0.72134752f);
    q = fmaf(q, t,  1.44269504f);
    return fmaf(t, q, ef);
}

// Scratch (no cudaMalloc allowed)
__device__ float    g_P1[NR * DD];   // p1 + eps
__device__ float    g_P2[NR * DD];   // p2 + eps
__device__ float    g_H1[NR];        // sum p1*ln(p1+eps)
__device__ float    g_H2[NR];
__device__ float    g_ptot[NBLK];    // per-block tot partials
__device__ float    g_pdia[NBLK];    // per-block dia partials
__device__ unsigned g_counter = 0;   // ticket for last-block finalize (self-resetting)

// One block per row; blocks [0,512) -> z1, [512,1024) -> z2. 256 threads, 3 elems each.
__global__ void softmax_kernel(const float* __restrict__ z1,
                               const float* __restrict__ z2) {
    const int  row   = blockIdx.x & (NR - 1);
    const bool first = blockIdx.x < NR;
    const float* src = (first ? z1 : z2) + row * DD;
    float*       dst = (first ? g_P1 : g_P2) + row * DD;
    float*      hrow = first ? g_H1 : g_H2;

    const int tid = threadIdx.x;
    const int w = tid >> 5, l = tid & 31;

    float x0 = src[tid];
    float x1 = src[tid + 256];
    float x2 = src[tid + 512];

    __shared__ float sred[8];

    float mx = fmaxf(x0, fmaxf(x1, x2));
    #pragma unroll
    for (int o = 16; o; o >>= 1) mx = fmaxf(mx, __shfl_xor_sync(0xffffffffu, mx, o));
    if (l == 0) sred[w] = mx;
    __syncthreads();
    mx = sred[0];
    #pragma unroll
    for (int i = 1; i < 8; i++) mx = fmaxf(mx, sred[i]);
    __syncthreads();

    const float L2E = 1.4426950408889634f;
    float e0 = fex2((x0 - mx) * L2E);
    float e1 = fex2((x1 - mx) * L2E);
    float e2 = fex2((x2 - mx) * L2E);
    float s = e0 + e1 + e2;
    #pragma unroll
    for (int o = 16; o; o >>= 1) s += __shfl_xor_sync(0xffffffffu, s, o);
    if (l == 0) sred[w] = s;
    __syncthreads();
    s = sred[0];
    #pragma unroll
    for (int i = 1; i < 8; i++) s += sred[i];
    __syncthreads();

    const float inv = 1.0f / s;
    float p0 = e0 * inv, p1 = e1 * inv, p2 = e2 * inv;
    float a0 = p0 + EPSF, a1 = p1 + EPSF, a2 = p2 + EPSF;
    dst[tid]       = a0;
    dst[tid + 256] = a1;
    dst[tid + 512] = a2;

    float h = p0 * flg2(a0) + p1 * flg2(a1) + p2 * flg2(a2);
    #pragma unroll
    for (int o = 16; o; o >>= 1) h += __shfl_xor_sync(0xffffffffu, h, o);
    if (l == 0) sred[w] = h;
    __syncthreads();
    if (tid == 0) {
        float hs = 0.f;
        #pragma unroll
        for (int i = 0; i < 8; i++) hs += sred[i];
        hrow[row] = hs * LN2F;
    }
}

// 16x16 pair tile per block, 128 threads (4 warps), each thread a 2x1 micro-tile.
// cp.async double-buffered k-pipeline; 17.4KB smem -> 7 blocks/SM -> the 1024-block
// grid is a SINGLE wave (148x7=1036), killing the 284-block tail seen at BK=96.
// 7 of 8 lg2 per quad via MUFU, 1 via FMA-pipe polynomial (12.5% off MUFU floor).
__global__ void __launch_bounds__(NT, 7) pair_kernel(float* __restrict__ out) {
    __shared__ float As[2][TI * PADF];
    __shared__ float Bs[2][TI * PADF];
    __shared__ float rt4[4], rd4[4];
    __shared__ bool  s_last;

    const int tid = threadIdx.x;
    const int ib = blockIdx.x & 31;   // 512/16 = 32 tiles per dim
    const int jb = blockIdx.x >> 5;
    const int ti = tid & 7;           // i rows: ti, ti+8
    const int tj = tid >> 3;          // j row: tj (0..15)

    const float4* gp1 = (const float4*)(g_P1 + ib * TI * DD);
    const float4* gp2 = (const float4*)(g_P2 + jb * TI * DD);

    // Per-chunk loads: 16x16=256 float4 per matrix, 128 threads -> 2 apiece
    int lrow[2], lcol[2];
    #pragma unroll
    for (int r = 0; r < 2; r++) {
        int idx = tid + r * NT;
        lrow[r] = idx >> 4;     // /16
        lcol[r] = idx & 15;
    }

    #define ISSUE_LOAD(kb, buf)                                                 \
    {                                                                           \
        _Pragma("unroll")                                                       \
        for (int r = 0; r < 2; r++) {                                           \
            int go = lrow[r] * (DD / 4) + (kb) * BK4 + lcol[r];                 \
            unsigned sa = (unsigned)__cvta_generic_to_shared(                   \
                &As[buf][lrow[r] * PADF + lcol[r] * 4]);                        \
            unsigned sb = (unsigned)__cvta_generic_to_shared(                   \
                &Bs[buf][lrow[r] * PADF + lcol[r] * 4]);                        \
            cp16(sa, gp1 + go);                                                 \
            cp16(sb, gp2 + go);                                                 \
        }                                                                       \
        asm volatile("cp.async.commit_group;");                                 \
    }

    // per pair (0 = row ti, 1 = row ti+8): T1 even/odd k accumulators
    float T1e0 = 0.f, T1o0 = 0.f, T1e1 = 0.f, T1o1 = 0.f;

    ISSUE_LOAD(0, 0);

    #pragma unroll 1
    for (int kb = 0; kb < NKB; kb++) {
        const int buf = kb & 1;
        if (kb + 1 < NKB) {
            ISSUE_LOAD(kb + 1, buf ^ 1);
            asm volatile("cp.async.wait_group 1;");
        } else {
            asm volatile("cp.async.wait_group 0;");
        }
        __syncthreads();

        const float4* a0p = (const float4*)(As[buf] + ti * PADF);
        const float4* a1p = (const float4*)(As[buf] + (ti + 8) * PADF);
        const float4* bp  = (const float4*)(Bs[buf] + tj * PADF);

        #pragma unroll
        for (int k = 0; k < BK4; k++) {
            float4 a0 = a0p[k], a1 = a1p[k];
            float4 b  = bp[k];

            // row 0 (ti): all 4 via MUFU
            {
                float s0 = a0.x + b.x;  float u0 = flg2(s0);
                float s1 = a0.y + b.y;  float u1 = flg2(s1);
                float s2 = a0.z + b.z;  float u2 = flg2(s2);
                float s3 = a0.w + b.w;  float u3 = flg2(s3);
                T1e0 = fmaf(s0, u0, T1e0);
                T1o0 = fmaf(s1, u1, T1o0);
                T1e0 = fmaf(s2, u2, T1e0);
                T1o0 = fmaf(s3, u3, T1o0);
            }
            // row 1 (ti+8): x,y,z via MUFU, w via FMA-pipe polynomial
            {
                float s0 = a1.x + b.x;  float u0 = flg2(s0);
                float s1 = a1.y + b.y;  float u1 = flg2(s1);
                float s2 = a1.z + b.z;  float u2 = flg2(s2);
                float s3 = a1.w + b.w;  float u3 = plg2(s3);
                T1e1 = fmaf(s0, u0, T1e1);
                T1o1 = fmaf(s1, u1, T1o1);
                T1e1 = fmaf(s2, u2, T1e1);
                T1o1 = fmaf(s3, u3, T1o1);
            }
        }
        __syncthreads();   // orders last reads of buf before it is overwritten
    }
    #undef ISSUE_LOAD

    const int gi0 = ib * TI + ti,  gi1 = gi0 + 8;
    const int gj  = jb * TI + tj;

    const float h10 = g_H1[gi0], h11 = g_H1[gi1];
    const float h2j = g_H2[gj];

    // C ~= ln2*(T1 - 2); jsd = 0.5*(H1 + H2 - C); eps correction is
    // common-mode and cancels in pos-neg (residual ~2e-8 abs).
    #define JSD(T1v, hi, hj) \
        (0.5f * ((hi) + (hj) - LN2F * ((T1v) - 2.0f)))
    float j0 = JSD(T1e0 + T1o0, h10, h2j);
    float j1 = JSD(T1e1 + T1o1, h11, h2j);
    #undef JSD

    float t = j0 + j1;
    float d = 0.f;
    if (gi0 == gj) d += j0;
    if (gi1 == gj) d += j1;

    const int w = tid >> 5, l = tid & 31;
    #pragma unroll
    for (int o = 16; o; o >>= 1) {
        t += __shfl_xor_sync(0xffffffffu, t, o);
        d += __shfl_xor_sync(0xffffffffu, d, o);
    }
    if (l == 0) { rt4[w] = t; rd4[w] = d; }
    __syncthreads();

    if (tid == 0) {
        g_ptot[blockIdx.x] = (rt4[0] + rt4[1]) + (rt4[2] + rt4[3]);
        g_pdia[blockIdx.x] = (rd4[0] + rd4[1]) + (rd4[2] + rd4[3]);
        __threadfence();
        unsigned ticket = atomicAdd(&g_counter, 1u);
        s_last = (ticket == (unsigned)(gridDim.x - 1));
    }
    __syncthreads();

    if (s_last) {
        double dt = 0.0, dd_ = 0.0;
        #pragma unroll
        for (int i = tid; i < NBLK; i += NT) {
            float pt = *(volatile float*)&g_ptot[i];
            float pd = *(volatile float*)&g_pdia[i];
            dt  += (double)pt;
            dd_ += (double)pd;
        }
        #pragma unroll
        for (int o = 16; o; o >>= 1) {
            dt  += __shfl_xor_sync(0xffffffffu, dt, o);
            dd_ += __shfl_xor_sync(0xffffffffu, dd_, o);
        }
        __shared__ double dtot[4], ddia[4];
        if (l == 0) { dtot[w] = dt; ddia[w] = dd_; }
        __syncthreads();
        if (tid == 0) {
            double tot  = (dtot[0] + dtot[1]) + (dtot[2] + dtot[3]);
            double dia_ = (ddia[0] + ddia[1]) + (ddia[2] + ddia[3]);
            double pos = dia_ / (double)NR;
            double neg = -(tot - dia_) / ((double)NR * NR - NR);
            out[0] = (float)(pos + (double)LAMBDF * neg);
            g_counter = 0;   // reset for next graph replay
        }
    }
}

extern "C" void kernel_launch(void* const* d_in, const int* in_sizes, int n_in,
                              void* d_out, int out_size) {
    const float* z1 = (const float*)d_in[0];
    const float* z2 = (const float*)d_in[1];
    float* out = (float*)d_out;

    softmax_kernel<<<2 * NR, 256>>>(z1, z2);
    pair_kernel<<<NBLK, NT>>>(out);
}